// round 15
// baseline (speedup 1.0000x reference)
#include <cuda_runtime.h>
#include <cuda_bf16.h>

// Problem constants
#define BB   64      // batch (inputs)
#define MM   256     // modes
#define KK   4096    // spatial (64*64)

#define KC      128  // K per CTA tile
#define KSPLIT  32   // KK / KC (norm + dot granularity)
#define MT      64   // modes per CTA
#define MTILES  4    // MM / MT
#define NTHR    256  // 8 warps = 2(m) x 2(n) x 2(k-half)
#define NCTA    (MTILES * KSPLIT)   // 128 CTAs, single co-resident wave
#define ROWF    132  // padded floats per smem row (conflict-free fragments)
#define ROW4    33   // float4 units per row
#define REDOFF  (2 * BB * ROWF)
#define SMEMB   ((2 * BB * ROWF + 4096) * 4)   // 83968 bytes
#define EPS_C   0.0009f

// Deterministic partial buffers (no cudaMalloc allowed)
__device__ __align__(16) float g_dot[KSPLIT * BB * MM];   // [s][b][m]  2 MB
__device__ __align__(16) float g_fss[KSPLIT * BB];        // [s][b] (all columns write identical bits)
__device__ __align__(16) float g_mss[KSPLIT * MM];        // [s][m]
__device__ __align__(16) float g_pmin[MTILES][BB];        // per-column partial min
__device__ unsigned int g_ccnt[MTILES];  // per-column arrival counters
__device__ unsigned int g_done;          // finalizer completions

__device__ __forceinline__ void cp_async16(void* smem, const void* gmem) {
    unsigned int s = (unsigned int)__cvta_generic_to_shared(smem);
    asm volatile("cp.async.cg.shared.global [%0], [%1], 16;"
                 :: "r"(s), "l"(gmem));
}

// mma.tf32 fed with RAW f32 bits (round-toward-zero tf32; CUTLASS-sanctioned).
__device__ __forceinline__ void mma_tf32(float& d0, float& d1, float& d2, float& d3,
                                         unsigned int a0, unsigned int a1,
                                         unsigned int a2, unsigned int a3,
                                         unsigned int b0, unsigned int b1) {
    asm volatile(
        "mma.sync.aligned.m16n8k8.row.col.f32.tf32.tf32.f32 "
        "{%0,%1,%2,%3}, {%4,%5,%6,%7}, {%8,%9}, {%0,%1,%2,%3};"
        : "+f"(d0), "+f"(d1), "+f"(d2), "+f"(d3)
        : "r"(a0), "r"(a1), "r"(a2), "r"(a3), "r"(b0), "r"(b1));
}

// Fused: tf32 tensor-core GEMM partials + per-column finalize + last-CTA combine.
__global__ __launch_bounds__(NTHR)
void fused_kernel(const float* __restrict__ inp,
                  const float* __restrict__ mds,
                  float* __restrict__ out) {
    extern __shared__ unsigned int su[];
    unsigned int* Au = su;                 // A tile: 64 x 132 raw f32 bits
    unsigned int* Bu = su + BB * ROWF;     // B tile: 64 x 132
    float4* racc = reinterpret_cast<float4*>(su + REDOFF);  // k-half reduction
    __shared__ float4 sd4[2][8][16];       // finalize: dot combine [bh][sg][q]
    __shared__ float4 sm4_[8][16];         // finalize: mss combine [sg][q]
    __shared__ float  sf[2][8];            // finalize: fss partial [bh][sg]
    __shared__ unsigned int s_rank;
    __shared__ int s_comb;

    const int mt = blockIdx.x;
    const int ks = blockIdx.y;
    const int kbase = ks * KC;
    const int mbase = mt * MT;
    const int tid  = threadIdx.x;
    const int lane = tid & 31;
    const int w    = tid >> 5;             // 0..7
    const int g    = lane >> 2;            // groupID 0..7
    const int tig  = lane & 3;             // thread-in-group 0..3

    uint4* Au4 = reinterpret_cast<uint4*>(Au);
    uint4* Bu4 = reinterpret_cast<uint4*>(Bu);

    // ---- stage A+B via cp.async ----
#pragma unroll
    for (int i = 0; i < 8; ++i) {
        int j  = i * NTHR + tid;
        int b  = j >> 5;
        int kq = j & 31;
        cp_async16(&Au4[b * ROW4 + kq],
                   reinterpret_cast<const float4*>(inp + (size_t)b * KK + kbase) + kq);
    }
#pragma unroll
    for (int i = 0; i < 8; ++i) {
        int j  = i * NTHR + tid;
        int m  = j >> 5;
        int kq = j & 31;
        cp_async16(&Bu4[m * ROW4 + kq],
                   reinterpret_cast<const float4*>(mds + (size_t)(mbase + m) * KK + kbase) + kq);
    }
    asm volatile("cp.async.commit_group;");
    asm volatile("cp.async.wait_group 0;");
    __syncthreads();

    // ---- tensor-core main loop: m32 x n32 x k64 warp tiles ----
    const int kh = w >> 2;                 // k-half 0/1
    const int wm = w & 1;                  // m-half
    const int wn = (w >> 1) & 1;           // n-half
    const int wp = w & 3;                  // warp-pair id (same for kh 0/1)
    const int r0 = wm * 32;                // A row base
    const int n0 = wn * 32;                // B col base (within 64-mode slice)
    const int kb = kh * 64;                // k base (floats)

    float acc[2][4][4];                    // [mi][t][frag]
#pragma unroll
    for (int mi = 0; mi < 2; ++mi)
#pragma unroll
        for (int t = 0; t < 4; ++t)
#pragma unroll
            for (int i = 0; i < 4; ++i) acc[mi][t][i] = 0.f;

#pragma unroll 4
    for (int kk = 0; kk < 8; ++kk) {
        const int acol = kb + kk * 8 + tig;
        unsigned int a[2][4];
#pragma unroll
        for (int mi = 0; mi < 2; ++mi) {
            int row = r0 + 16 * mi + g;
            a[mi][0] = Au[row       * ROWF + acol];
            a[mi][1] = Au[(row + 8) * ROWF + acol];
            a[mi][2] = Au[row       * ROWF + acol + 4];
            a[mi][3] = Au[(row + 8) * ROWF + acol + 4];
        }
#pragma unroll
        for (int t = 0; t < 4; ++t) {
            int n = n0 + t * 8 + g;
            unsigned int b0 = Bu[n * ROWF + kb + kk * 8 + tig];
            unsigned int b1 = Bu[n * ROWF + kb + kk * 8 + tig + 4];
#pragma unroll
            for (int mi = 0; mi < 2; ++mi)
                mma_tf32(acc[mi][t][0], acc[mi][t][1], acc[mi][t][2], acc[mi][t][3],
                         a[mi][0], a[mi][1], a[mi][2], a[mi][3], b0, b1);
        }
    }

    // ---- k-half reduction in smem: kh=1 stores, kh=0 adds ----
    if (kh == 1) {
#pragma unroll
        for (int mi = 0; mi < 2; ++mi)
#pragma unroll
            for (int t = 0; t < 4; ++t)
                racc[(wp * 8 + mi * 4 + t) * 32 + lane] =
                    make_float4(acc[mi][t][0], acc[mi][t][1],
                                acc[mi][t][2], acc[mi][t][3]);
    }
    __syncthreads();

    if (kh == 0) {
        // ---- epilogue: full-tile dot, split slot = ks ----
#pragma unroll
        for (int mi = 0; mi < 2; ++mi)
#pragma unroll
            for (int t = 0; t < 4; ++t) {
                float4 o = racc[(wp * 8 + mi * 4 + t) * 32 + lane];
                float d0 = acc[mi][t][0] + o.x;
                float d1 = acc[mi][t][1] + o.y;
                float d2 = acc[mi][t][2] + o.z;
                float d3 = acc[mi][t][3] + o.w;
                int row = r0 + 16 * mi + g;
                int m = mbase + n0 + t * 8 + 2 * tig;
                *reinterpret_cast<float2*>(&g_dot[((size_t)ks * BB + row)     * MM + m]) =
                    make_float2(d0, d1);
                *reinterpret_cast<float2*>(&g_dot[((size_t)ks * BB + row + 8) * MM + m]) =
                    make_float2(d2, d3);
            }
    }

    // ---- partial squared norms from RAW f32 tiles (warp per row) ----
    const float4* Af4 = reinterpret_cast<const float4*>(Au);
    const float4* Bf4 = reinterpret_cast<const float4*>(Bu);
#pragma unroll
    for (int r = 0; r < 8; ++r) {
        int m = 8 * w + r;
        float4 v = Bf4[m * ROW4 + lane];
        float s = v.x * v.x + v.y * v.y + v.z * v.z + v.w * v.w;
#pragma unroll
        for (int o = 16; o > 0; o >>= 1) s += __shfl_xor_sync(0xffffffffu, s, o);
        if (lane == 0) g_mss[ks * MM + mbase + m] = s;
    }
    // fss: EVERY column writes bitwise-identical values (benign) so each
    // column's finalizers depend only on their own 32 CTAs.
#pragma unroll
    for (int r = 0; r < 8; ++r) {
        int b = 8 * w + r;
        float4 v = Af4[b * ROW4 + lane];
        float s = v.x * v.x + v.y * v.y + v.z * v.z + v.w * v.w;
#pragma unroll
        for (int o = 16; o > 0; o >>= 1) s += __shfl_xor_sync(0xffffffffu, s, o);
        if (lane == 0) g_fss[ks * BB + b] = s;
    }

    // ---- per-column arrival + poll (column's 32 CTAs only) ----
    __syncthreads();
    if (tid == 0) {
        __threadfence();                                   // publish partials
        s_rank = atomicAdd(&g_ccnt[mt], 1u);               // rank within column
        unsigned int v;
        do {
            asm volatile("ld.acquire.gpu.u32 %0, [%1];" : "=r"(v) : "l"(&g_ccnt[mt]));
        } while (v < KSPLIT);
    }
    __syncthreads();
    const unsigned int rank = s_rank;                      // 0..31

    // ---- finalize: CTA handles b = 2*rank + bh over this column's 64 modes ----
    // stage 1: thread t = (bh, sg, q): sum 4 splits
    {
        const int bh = tid >> 7;                           // 0/1
        const int r  = tid & 127;
        const int sg = r >> 4;                             // 0..7 (4 splits each)
        const int q  = r & 15;                             // m-quad within column
        const int b  = 2 * (int)rank + bh;
        const int col4 = mt * 16 + q;

        const float4* dot4 = reinterpret_cast<const float4*>(g_dot);
        const float4* mss4 = reinterpret_cast<const float4*>(g_mss);

        float4 d  = make_float4(0.f, 0.f, 0.f, 0.f);
        float4 ms = make_float4(0.f, 0.f, 0.f, 0.f);
        float  fs = 0.f;
#pragma unroll
        for (int i = 0; i < 4; ++i) {
            int s = sg * 4 + i;
            float4 v = dot4[((size_t)s * BB + b) * (MM / 4) + col4];
            d.x += v.x; d.y += v.y; d.z += v.z; d.w += v.w;
            float4 u = mss4[s * (MM / 4) + col4];
            ms.x += u.x; ms.y += u.y; ms.z += u.z; ms.w += u.w;
            fs += g_fss[s * BB + b];
        }
        sd4[bh][sg][q] = d;
        if (bh == 0) sm4_[sg][q] = ms;
        if (q == 0) sf[bh][sg] = fs;
    }
    __syncthreads();

    // stage 2: warp 0: lane = (bh=lane>>4, q=lane&15)
    if (w == 0) {
        const int bh = lane >> 4;
        const int q  = lane & 15;
        const int b  = 2 * (int)rank + bh;

        float dot[4] = {0.f, 0.f, 0.f, 0.f};
        float mss[4] = {0.f, 0.f, 0.f, 0.f};
        float fss = 0.f;
#pragma unroll
        for (int i = 0; i < 8; ++i) {
            float4 dv = sd4[bh][i][q];
            float4 mv = sm4_[i][q];
            dot[0] += dv.x; dot[1] += dv.y; dot[2] += dv.z; dot[3] += dv.w;
            mss[0] += mv.x; mss[1] += mv.y; mss[2] += mv.z; mss[3] += mv.w;
            fss += sf[bh][i];
        }
        float fn = sqrtf(fss);

        float best = 3.4e38f;
#pragma unroll
        for (int i = 0; i < 4; ++i) {
            float mn = sqrtf(mss[i]);
            float cc = dot[i] / (fn * mn);
            float dn = sqrtf(fmaxf(2.f - 2.f * cc, 0.f));
            float lum = (2.f * fn * mn + EPS_C) / (fss + mss[i] + EPS_C);
            float metric = (1.f - (2.f - dn) * 0.5f * sqrtf(lum)) * 2.f;
            best = fminf(best, metric);
        }
        // min across the 16 lanes of this half (xor < 16 keeps bit4 fixed)
#pragma unroll
        for (int o = 8; o > 0; o >>= 1)
            best = fminf(best, __shfl_xor_sync(0xffffffffu, best, o));
        if ((lane & 15) == 0) g_pmin[mt][b] = best;        // deterministic store
    }
    __syncthreads();

    // ---- completion: the 128th finalizer combines columns and resets ----
    if (tid == 0) {
        __threadfence();                                   // publish g_pmin
        s_comb = (atomicAdd(&g_done, 1u) == NCTA - 1);
    }
    __syncthreads();
    if (s_comb) {
        __threadfence();                                   // see all g_pmin
        if (tid < BB) {
            float v = fminf(fminf(g_pmin[0][tid], g_pmin[1][tid]),
                            fminf(g_pmin[2][tid], g_pmin[3][tid]));
            out[tid] = v;
        }
        __syncthreads();
        if (tid == 0) {                                    // reset for next replay
            g_done = 0u;
            g_ccnt[0] = 0u; g_ccnt[1] = 0u; g_ccnt[2] = 0u; g_ccnt[3] = 0u;
            __threadfence();
        }
    }
}

extern "C" void kernel_launch(void* const* d_in, const int* in_sizes, int n_in,
                              void* d_out, int out_size) {
    const float* inp = (const float*)d_in[0];
    const float* mds = (const float*)d_in[1];
    if (in_sizes[0] > in_sizes[1]) {   // identify by element count
        const float* t = inp; inp = mds; mds = t;
    }

    cudaFuncSetAttribute(fused_kernel,
                         cudaFuncAttributeMaxDynamicSharedMemorySize, SMEMB);

    dim3 grid(MTILES, KSPLIT);         // 4 x 32 = 128 CTAs, single wave
    fused_kernel<<<grid, NTHR, SMEMB>>>(inp, mds, (float*)d_out);
}

// round 16
// speedup vs baseline: 1.0445x; 1.0445x over previous
#include <cuda_runtime.h>
#include <cuda_bf16.h>

// Problem constants
#define BB   64      // batch (inputs)
#define MM   256     // modes
#define KK   4096    // spatial (64*64)

#define KC      128  // K per CTA tile
#define KSPLIT  32   // KK / KC (norm + dot granularity)
#define MT      64   // modes per CTA
#define MTILES  4    // MM / MT
#define NTHR    256  // 8 warps = 2(m) x 2(n) x 2(k-half)
#define NCTA    (MTILES * KSPLIT)   // 128 CTAs, single co-resident wave
#define ROWF    132  // padded floats per smem row (conflict-free fragments)
#define ROW4    33   // float4 units per row
#define REDOFF  (2 * BB * ROWF)
#define SMEMB   ((2 * BB * ROWF + 4096) * 4)   // 83968 bytes
#define EPS_C   0.0009f

// Deterministic partial buffers (no cudaMalloc allowed)
__device__ __align__(16) float g_dot[KSPLIT * BB * MM];   // [s][b][m]  2 MB
__device__ __align__(16) float g_fss[KSPLIT * BB];        // [s][b]
__device__ __align__(16) float g_mss[KSPLIT * MM];        // [s][m]
__device__ unsigned int g_cnt;    // arrival counter (reset by last finalizer)
__device__ unsigned int g_done;   // tail-done counter

__device__ __forceinline__ void cp_async16(void* smem, const void* gmem) {
    unsigned int s = (unsigned int)__cvta_generic_to_shared(smem);
    asm volatile("cp.async.cg.shared.global [%0], [%1], 16;"
                 :: "r"(s), "l"(gmem));
}

// mma.tf32 fed with RAW f32 bits (round-toward-zero tf32; CUTLASS-sanctioned).
__device__ __forceinline__ void mma_tf32(float& d0, float& d1, float& d2, float& d3,
                                         unsigned int a0, unsigned int a1,
                                         unsigned int a2, unsigned int a3,
                                         unsigned int b0, unsigned int b1) {
    asm volatile(
        "mma.sync.aligned.m16n8k8.row.col.f32.tf32.tf32.f32 "
        "{%0,%1,%2,%3}, {%4,%5,%6,%7}, {%8,%9}, {%0,%1,%2,%3};"
        : "+f"(d0), "+f"(d1), "+f"(d2), "+f"(d3)
        : "r"(a0), "r"(a1), "r"(a2), "r"(a3), "r"(b0), "r"(b1));
}

// Fused: tf32 tensor-core GEMM partials + all-128-CTA finalize
// (static assignment: CTA lid handles b = lid&63, mode-half = lid>>6).
__global__ __launch_bounds__(NTHR)
void fused_kernel(const float* __restrict__ inp,
                  const float* __restrict__ mds,
                  unsigned int* __restrict__ outu) {
    extern __shared__ unsigned int su[];
    unsigned int* Au = su;                 // A tile: 64 x 132 raw f32 bits
    unsigned int* Bu = su + BB * ROWF;     // B tile: 64 x 132
    float4* racc = reinterpret_cast<float4*>(su + REDOFF);  // k-half reduction
    __shared__ float4 sd4[8][32];          // finalize: dot combine
    __shared__ float4 sm4[8][32];          // finalize: mss combine
    __shared__ float  sf[8];

    const int mt = blockIdx.x;
    const int ks = blockIdx.y;
    const int kbase = ks * KC;
    const int mbase = mt * MT;
    const int tid  = threadIdx.x;
    const int lane = tid & 31;
    const int w    = tid >> 5;             // 0..7
    const int g    = lane >> 2;            // groupID 0..7
    const int tig  = lane & 3;             // thread-in-group 0..3

    // per-replay out init (visible to finalizers via the arrival fence below)
    if (mt == 0 && ks == 0 && tid < BB) outu[tid] = 0x7f7f7f7fu;

    uint4* Au4 = reinterpret_cast<uint4*>(Au);
    uint4* Bu4 = reinterpret_cast<uint4*>(Bu);

    // ---- stage A+B via cp.async ----
#pragma unroll
    for (int i = 0; i < 8; ++i) {
        int j  = i * NTHR + tid;
        int b  = j >> 5;
        int kq = j & 31;
        cp_async16(&Au4[b * ROW4 + kq],
                   reinterpret_cast<const float4*>(inp + (size_t)b * KK + kbase) + kq);
    }
#pragma unroll
    for (int i = 0; i < 8; ++i) {
        int j  = i * NTHR + tid;
        int m  = j >> 5;
        int kq = j & 31;
        cp_async16(&Bu4[m * ROW4 + kq],
                   reinterpret_cast<const float4*>(mds + (size_t)(mbase + m) * KK + kbase) + kq);
    }
    asm volatile("cp.async.commit_group;");
    asm volatile("cp.async.wait_group 0;");
    __syncthreads();

    // ---- tensor-core main loop: m32 x n32 x k64 warp tiles ----
    const int kh = w >> 2;                 // k-half 0/1
    const int wm = w & 1;                  // m-half
    const int wn = (w >> 1) & 1;           // n-half
    const int wp = w & 3;                  // warp-pair id (same for kh 0/1)
    const int r0 = wm * 32;                // A row base
    const int n0 = wn * 32;                // B col base (within 64-mode slice)
    const int kb = kh * 64;                // k base (floats)

    float acc[2][4][4];                    // [mi][t][frag]
#pragma unroll
    for (int mi = 0; mi < 2; ++mi)
#pragma unroll
        for (int t = 0; t < 4; ++t)
#pragma unroll
            for (int i = 0; i < 4; ++i) acc[mi][t][i] = 0.f;

#pragma unroll 4
    for (int kk = 0; kk < 8; ++kk) {
        const int acol = kb + kk * 8 + tig;
        unsigned int a[2][4];
#pragma unroll
        for (int mi = 0; mi < 2; ++mi) {
            int row = r0 + 16 * mi + g;
            a[mi][0] = Au[row       * ROWF + acol];
            a[mi][1] = Au[(row + 8) * ROWF + acol];
            a[mi][2] = Au[row       * ROWF + acol + 4];
            a[mi][3] = Au[(row + 8) * ROWF + acol + 4];
        }
#pragma unroll
        for (int t = 0; t < 4; ++t) {
            int n = n0 + t * 8 + g;
            unsigned int b0 = Bu[n * ROWF + kb + kk * 8 + tig];
            unsigned int b1 = Bu[n * ROWF + kb + kk * 8 + tig + 4];
#pragma unroll
            for (int mi = 0; mi < 2; ++mi)
                mma_tf32(acc[mi][t][0], acc[mi][t][1], acc[mi][t][2], acc[mi][t][3],
                         a[mi][0], a[mi][1], a[mi][2], a[mi][3], b0, b1);
        }
    }

    // ---- k-half reduction in smem: kh=1 stores, kh=0 adds ----
    if (kh == 1) {
#pragma unroll
        for (int mi = 0; mi < 2; ++mi)
#pragma unroll
            for (int t = 0; t < 4; ++t)
                racc[(wp * 8 + mi * 4 + t) * 32 + lane] =
                    make_float4(acc[mi][t][0], acc[mi][t][1],
                                acc[mi][t][2], acc[mi][t][3]);
    }
    __syncthreads();

    if (kh == 0) {
        // ---- epilogue: full-tile dot, split slot = ks ----
#pragma unroll
        for (int mi = 0; mi < 2; ++mi)
#pragma unroll
            for (int t = 0; t < 4; ++t) {
                float4 o = racc[(wp * 8 + mi * 4 + t) * 32 + lane];
                float d0 = acc[mi][t][0] + o.x;
                float d1 = acc[mi][t][1] + o.y;
                float d2 = acc[mi][t][2] + o.z;
                float d3 = acc[mi][t][3] + o.w;
                int row = r0 + 16 * mi + g;
                int m = mbase + n0 + t * 8 + 2 * tig;
                *reinterpret_cast<float2*>(&g_dot[((size_t)ks * BB + row)     * MM + m]) =
                    make_float2(d0, d1);
                *reinterpret_cast<float2*>(&g_dot[((size_t)ks * BB + row + 8) * MM + m]) =
                    make_float2(d2, d3);
            }
    }

    // ---- partial squared norms from RAW f32 tiles (warp per row) ----
    const float4* Af4 = reinterpret_cast<const float4*>(Au);
    const float4* Bf4 = reinterpret_cast<const float4*>(Bu);
#pragma unroll
    for (int r = 0; r < 8; ++r) {
        int m = 8 * w + r;
        float4 v = Bf4[m * ROW4 + lane];
        float s = v.x * v.x + v.y * v.y + v.z * v.z + v.w * v.w;
#pragma unroll
        for (int o = 16; o > 0; o >>= 1) s += __shfl_xor_sync(0xffffffffu, s, o);
        if (lane == 0) g_mss[ks * MM + mbase + m] = s;
    }
    if (mt == 0) {
#pragma unroll
        for (int r = 0; r < 8; ++r) {
            int b = 8 * w + r;
            float4 v = Af4[b * ROW4 + lane];
            float s = v.x * v.x + v.y * v.y + v.z * v.z + v.w * v.w;
#pragma unroll
            for (int o = 16; o > 0; o >>= 1) s += __shfl_xor_sync(0xffffffffu, s, o);
            if (lane == 0) g_fss[ks * BB + b] = s;
        }
    }

    // ---- arrival + direct-poll release (single global hop) ----
    __syncthreads();
    if (tid == 0) {
        __threadfence();                                   // publish partials
        atomicAdd(&g_cnt, 1u);
        unsigned int v;
        do {                                               // wait for all arrivals
            asm volatile("ld.acquire.gpu.u32 %0, [%1];" : "=r"(v) : "l"(&g_cnt));
        } while (v < NCTA);
    }
    __syncthreads();

    // ---- finalize (static): CTA lid handles b = lid&63, mode-half = lid>>6 ----
    const int lid = ks * MTILES + mt;                      // 0..127
    const int b   = lid & 63;
    const int mh  = lid >> 6;                              // 0/1
    const int q   = mh * 32 + lane;                        // m-quad in [0,64)
    const int sg  = w;                                     // split-group 0..7

    const float4* dot4 = reinterpret_cast<const float4*>(g_dot);
    const float4* mss4 = reinterpret_cast<const float4*>(g_mss);

    float4 d  = make_float4(0.f, 0.f, 0.f, 0.f);
    float4 ms = make_float4(0.f, 0.f, 0.f, 0.f);
    float  fs = 0.f;
#pragma unroll
    for (int i = 0; i < 4; ++i) {                          // 4 of 32 splits
        int s = sg * 4 + i;
        float4 v = dot4[((size_t)s * BB + b) * (MM / 4) + q];
        d.x += v.x; d.y += v.y; d.z += v.z; d.w += v.w;
        float4 u = mss4[s * (MM / 4) + q];
        ms.x += u.x; ms.y += u.y; ms.z += u.z; ms.w += u.w;
        fs += g_fss[s * BB + b];                           // uniform -> broadcast
    }
    sd4[sg][lane] = d;
    sm4[sg][lane] = ms;
    if (lane == 0) sf[sg] = fs;
    __syncthreads();

    if (w == 0) {                                          // one warp combines
        float dot[4] = {0.f, 0.f, 0.f, 0.f};
        float mss[4] = {0.f, 0.f, 0.f, 0.f};
        float fss = 0.f;
#pragma unroll
        for (int i = 0; i < 8; ++i) {
            float4 dv = sd4[i][lane];
            float4 mv = sm4[i][lane];
            dot[0] += dv.x; dot[1] += dv.y; dot[2] += dv.z; dot[3] += dv.w;
            mss[0] += mv.x; mss[1] += mv.y; mss[2] += mv.z; mss[3] += mv.w;
            fss += sf[i];
        }
        float fn = sqrtf(fss);

        float best = 3.4e38f;
#pragma unroll
        for (int i = 0; i < 4; ++i) {
            float mn = sqrtf(mss[i]);
            float cc = dot[i] / (fn * mn);
            float dn = sqrtf(fmaxf(2.f - 2.f * cc, 0.f));
            float lum = (2.f * fn * mn + EPS_C) / (fss + mss[i] + EPS_C);
            float metric = (1.f - (2.f - dn) * 0.5f * sqrtf(lum)) * 2.f;
            best = fminf(best, metric);
        }
#pragma unroll
        for (int o = 16; o > 0; o >>= 1)
            best = fminf(best, __shfl_xor_sync(0xffffffffu, best, o));
        if (lane == 0) {
            atomicMin(&outu[b], __float_as_uint(best));    // nonneg: uint==float order

            unsigned int dn = atomicAdd(&g_done, 1u);      // last finalizer resets
            if (dn == NCTA - 1) {
                g_done = 0u;
                atomicExch(&g_cnt, 0u);
            }
        }
    }
}

extern "C" void kernel_launch(void* const* d_in, const int* in_sizes, int n_in,
                              void* d_out, int out_size) {
    const float* inp = (const float*)d_in[0];
    const float* mds = (const float*)d_in[1];
    if (in_sizes[0] > in_sizes[1]) {   // identify by element count
        const float* t = inp; inp = mds; mds = t;
    }

    cudaFuncSetAttribute(fused_kernel,
                         cudaFuncAttributeMaxDynamicSharedMemorySize, SMEMB);

    dim3 grid(MTILES, KSPLIT);         // 4 x 32 = 128 CTAs, single wave
    fused_kernel<<<grid, NTHR, SMEMB>>>(inp, mds, (unsigned int*)d_out);
}

// round 17
// speedup vs baseline: 1.1875x; 1.1369x over previous
#include <cuda_runtime.h>
#include <cuda_bf16.h>

// Problem constants
#define BB   64      // batch (inputs)
#define MM   256     // modes
#define KK   4096    // spatial (64*64)

#define KC      128  // K per CTA tile
#define KSPLIT  32   // KK / KC (norm + dot granularity)
#define MT      64   // modes per CTA
#define MTILES  4    // MM / MT
#define NTHR    256  // 8 warps = 2(m) x 2(n) x 2(k-half)
#define NCTA    (MTILES * KSPLIT)   // 128 CTAs, single co-resident wave
#define ROWF    132  // padded floats per smem row (conflict-free fragments)
#define ROW4    33   // float4 units per row
#define REDOFF  (2 * BB * ROWF)
#define SMEMB   ((2 * BB * ROWF + 4096) * 4)   // 83968 bytes
#define EPS_C   0.0009f

// Deterministic partial buffers (no cudaMalloc allowed)
__device__ __align__(16) float g_dot[KSPLIT * BB * MM];   // [s][b][m]  2 MB
__device__ __align__(16) float g_fss[KSPLIT * BB];        // [s][b]
__device__ __align__(16) float g_mss[KSPLIT * MM];        // [s][m]
__device__ unsigned int g_cnt;    // arrival counter (reset by last finalizer)
__device__ unsigned int g_done;   // tail-done counter

__device__ __forceinline__ void cp_async16(void* smem, const void* gmem) {
    unsigned int s = (unsigned int)__cvta_generic_to_shared(smem);
    asm volatile("cp.async.cg.shared.global [%0], [%1], 16;"
                 :: "r"(s), "l"(gmem));
}

// mma.tf32 fed with RAW f32 bits (round-toward-zero tf32; CUTLASS-sanctioned).
__device__ __forceinline__ void mma_tf32(float& d0, float& d1, float& d2, float& d3,
                                         unsigned int a0, unsigned int a1,
                                         unsigned int a2, unsigned int a3,
                                         unsigned int b0, unsigned int b1) {
    asm volatile(
        "mma.sync.aligned.m16n8k8.row.col.f32.tf32.tf32.f32 "
        "{%0,%1,%2,%3}, {%4,%5,%6,%7}, {%8,%9}, {%0,%1,%2,%3};"
        : "+f"(d0), "+f"(d1), "+f"(d2), "+f"(d3)
        : "r"(a0), "r"(a1), "r"(a2), "r"(a3), "r"(b0), "r"(b1));
}

// Fused: tf32 tensor-core GEMM partials + all-128-CTA finalize
// (each CTA: one b, one 128-mode half; atomicMin into out).
__global__ __launch_bounds__(NTHR)
void fused_kernel(const float* __restrict__ inp,
                  const float* __restrict__ mds,
                  unsigned int* __restrict__ outu) {
    extern __shared__ unsigned int su[];
    unsigned int* Au = su;                 // A tile: 64 x 132 raw f32 bits
    unsigned int* Bu = su + BB * ROWF;     // B tile: 64 x 132
    float4* racc = reinterpret_cast<float4*>(su + REDOFF);  // k-half reduction
    __shared__ float4 sd4[8][32];          // finalize: dot combine
    __shared__ float4 sm4[8][32];          // finalize: mss combine
    __shared__ float  sf[8];
    __shared__ unsigned int s_rank;

    const int mt = blockIdx.x;
    const int ks = blockIdx.y;
    const int kbase = ks * KC;
    const int mbase = mt * MT;
    const int tid  = threadIdx.x;
    const int lane = tid & 31;
    const int w    = tid >> 5;             // 0..7
    const int g    = lane >> 2;            // groupID 0..7
    const int tig  = lane & 3;             // thread-in-group 0..3

    // per-replay out init (visible to finalizers via the arrival fence below)
    if (mt == 0 && ks == 0 && tid < BB) outu[tid] = 0x7f7f7f7fu;

    uint4* Au4 = reinterpret_cast<uint4*>(Au);
    uint4* Bu4 = reinterpret_cast<uint4*>(Bu);

    // ---- stage A+B via cp.async ----
#pragma unroll
    for (int i = 0; i < 8; ++i) {
        int j  = i * NTHR + tid;
        int b  = j >> 5;
        int kq = j & 31;
        cp_async16(&Au4[b * ROW4 + kq],
                   reinterpret_cast<const float4*>(inp + (size_t)b * KK + kbase) + kq);
    }
#pragma unroll
    for (int i = 0; i < 8; ++i) {
        int j  = i * NTHR + tid;
        int m  = j >> 5;
        int kq = j & 31;
        cp_async16(&Bu4[m * ROW4 + kq],
                   reinterpret_cast<const float4*>(mds + (size_t)(mbase + m) * KK + kbase) + kq);
    }
    asm volatile("cp.async.commit_group;");
    asm volatile("cp.async.wait_group 0;");
    __syncthreads();

    // ---- tensor-core main loop: m32 x n32 x k64 warp tiles ----
    const int kh = w >> 2;                 // k-half 0/1
    const int wm = w & 1;                  // m-half
    const int wn = (w >> 1) & 1;           // n-half
    const int wp = w & 3;                  // warp-pair id (same for kh 0/1)
    const int r0 = wm * 32;                // A row base
    const int n0 = wn * 32;                // B col base (within 64-mode slice)
    const int kb = kh * 64;                // k base (floats)

    float acc[2][4][4];                    // [mi][t][frag]
#pragma unroll
    for (int mi = 0; mi < 2; ++mi)
#pragma unroll
        for (int t = 0; t < 4; ++t)
#pragma unroll
            for (int i = 0; i < 4; ++i) acc[mi][t][i] = 0.f;

#pragma unroll 4
    for (int kk = 0; kk < 8; ++kk) {
        const int acol = kb + kk * 8 + tig;
        unsigned int a[2][4];
#pragma unroll
        for (int mi = 0; mi < 2; ++mi) {
            int row = r0 + 16 * mi + g;
            a[mi][0] = Au[row       * ROWF + acol];
            a[mi][1] = Au[(row + 8) * ROWF + acol];
            a[mi][2] = Au[row       * ROWF + acol + 4];
            a[mi][3] = Au[(row + 8) * ROWF + acol + 4];
        }
#pragma unroll
        for (int t = 0; t < 4; ++t) {
            int n = n0 + t * 8 + g;
            unsigned int b0 = Bu[n * ROWF + kb + kk * 8 + tig];
            unsigned int b1 = Bu[n * ROWF + kb + kk * 8 + tig + 4];
#pragma unroll
            for (int mi = 0; mi < 2; ++mi)
                mma_tf32(acc[mi][t][0], acc[mi][t][1], acc[mi][t][2], acc[mi][t][3],
                         a[mi][0], a[mi][1], a[mi][2], a[mi][3], b0, b1);
        }
    }

    // ---- k-half reduction in smem: kh=1 stores, kh=0 adds ----
    if (kh == 1) {
#pragma unroll
        for (int mi = 0; mi < 2; ++mi)
#pragma unroll
            for (int t = 0; t < 4; ++t)
                racc[(wp * 8 + mi * 4 + t) * 32 + lane] =
                    make_float4(acc[mi][t][0], acc[mi][t][1],
                                acc[mi][t][2], acc[mi][t][3]);
    }
    __syncthreads();

    if (kh == 0) {
        // ---- epilogue: full-tile dot, split slot = ks ----
#pragma unroll
        for (int mi = 0; mi < 2; ++mi)
#pragma unroll
            for (int t = 0; t < 4; ++t) {
                float4 o = racc[(wp * 8 + mi * 4 + t) * 32 + lane];
                float d0 = acc[mi][t][0] + o.x;
                float d1 = acc[mi][t][1] + o.y;
                float d2 = acc[mi][t][2] + o.z;
                float d3 = acc[mi][t][3] + o.w;
                int row = r0 + 16 * mi + g;
                int m = mbase + n0 + t * 8 + 2 * tig;
                *reinterpret_cast<float2*>(&g_dot[((size_t)ks * BB + row)     * MM + m]) =
                    make_float2(d0, d1);
                *reinterpret_cast<float2*>(&g_dot[((size_t)ks * BB + row + 8) * MM + m]) =
                    make_float2(d2, d3);
            }
    }

    // ---- partial squared norms from RAW f32 tiles (warp per row) ----
    const float4* Af4 = reinterpret_cast<const float4*>(Au);
    const float4* Bf4 = reinterpret_cast<const float4*>(Bu);
#pragma unroll
    for (int r = 0; r < 8; ++r) {
        int m = 8 * w + r;
        float4 v = Bf4[m * ROW4 + lane];
        float s = v.x * v.x + v.y * v.y + v.z * v.z + v.w * v.w;
#pragma unroll
        for (int o = 16; o > 0; o >>= 1) s += __shfl_xor_sync(0xffffffffu, s, o);
        if (lane == 0) g_mss[ks * MM + mbase + m] = s;
    }
    if (mt == 0) {
#pragma unroll
        for (int r = 0; r < 8; ++r) {
            int b = 8 * w + r;
            float4 v = Af4[b * ROW4 + lane];
            float s = v.x * v.x + v.y * v.y + v.z * v.z + v.w * v.w;
#pragma unroll
            for (int o = 16; o > 0; o >>= 1) s += __shfl_xor_sync(0xffffffffu, s, o);
            if (lane == 0) g_fss[ks * BB + b] = s;
        }
    }

    // ---- arrival + direct-poll release (no separate flag hop) ----
    __syncthreads();
    if (tid == 0) {
        __threadfence();                                   // publish partials
        s_rank = atomicAdd(&g_cnt, 1u);                    // arrival rank
        unsigned int v;
        do {                                               // wait for all arrivals
            asm volatile("ld.acquire.gpu.u32 %0, [%1];" : "=r"(v) : "l"(&g_cnt));
        } while (v < NCTA);
    }
    __syncthreads();
    const unsigned int rank = s_rank;

    // ---- finalize: CTA handles b = rank&63, mode-half mh = rank>>6 ----
    const int b  = rank & 63;
    const int mh = rank >> 6;                              // 0/1
    const int q  = mh * 32 + lane;                         // m-quad in [0,64)
    const int sg = w;                                      // split-group 0..7

    const float4* dot4 = reinterpret_cast<const float4*>(g_dot);
    const float4* mss4 = reinterpret_cast<const float4*>(g_mss);

    float4 d  = make_float4(0.f, 0.f, 0.f, 0.f);
    float4 ms = make_float4(0.f, 0.f, 0.f, 0.f);
    float  fs = 0.f;
#pragma unroll
    for (int i = 0; i < 4; ++i) {                          // 4 of 32 splits
        int s = sg * 4 + i;
        float4 v = dot4[((size_t)s * BB + b) * (MM / 4) + q];
        d.x += v.x; d.y += v.y; d.z += v.z; d.w += v.w;
        float4 u = mss4[s * (MM / 4) + q];
        ms.x += u.x; ms.y += u.y; ms.z += u.z; ms.w += u.w;
        fs += g_fss[s * BB + b];                           // uniform -> broadcast
    }
    sd4[sg][lane] = d;
    sm4[sg][lane] = ms;
    if (lane == 0) sf[sg] = fs;
    __syncthreads();

    if (w == 0) {                                          // one warp combines
        float dot[4] = {0.f, 0.f, 0.f, 0.f};
        float mss[4] = {0.f, 0.f, 0.f, 0.f};
        float fss = 0.f;
#pragma unroll
        for (int i = 0; i < 8; ++i) {
            float4 dv = sd4[i][lane];
            float4 mv = sm4[i][lane];
            dot[0] += dv.x; dot[1] += dv.y; dot[2] += dv.z; dot[3] += dv.w;
            mss[0] += mv.x; mss[1] += mv.y; mss[2] += mv.z; mss[3] += mv.w;
            fss += sf[i];
        }
        float fn = sqrtf(fss);

        float best = 3.4e38f;
#pragma unroll
        for (int i = 0; i < 4; ++i) {
            float mn = sqrtf(mss[i]);
            float cc = dot[i] / (fn * mn);
            float dn = sqrtf(fmaxf(2.f - 2.f * cc, 0.f));
            float lum = (2.f * fn * mn + EPS_C) / (fss + mss[i] + EPS_C);
            float metric = (1.f - (2.f - dn) * 0.5f * sqrtf(lum)) * 2.f;
            best = fminf(best, metric);
        }
#pragma unroll
        for (int o = 16; o > 0; o >>= 1)
            best = fminf(best, __shfl_xor_sync(0xffffffffu, best, o));
        if (lane == 0) {
            atomicMin(&outu[b], __float_as_uint(best));    // nonneg: uint==float order

            unsigned int dn = atomicAdd(&g_done, 1u);      // last finalizer resets
            if (dn == NCTA - 1) {
                g_done = 0u;
                atomicExch(&g_cnt, 0u);
            }
        }
    }
}

extern "C" void kernel_launch(void* const* d_in, const int* in_sizes, int n_in,
                              void* d_out, int out_size) {
    const float* inp = (const float*)d_in[0];
    const float* mds = (const float*)d_in[1];
    if (in_sizes[0] > in_sizes[1]) {   // identify by element count
        const float* t = inp; inp = mds; mds = t;
    }

    cudaFuncSetAttribute(fused_kernel,
                         cudaFuncAttributeMaxDynamicSharedMemorySize, SMEMB);

    dim3 grid(MTILES, KSPLIT);         // 4 x 32 = 128 CTAs, single wave
    fused_kernel<<<grid, NTHR, SMEMB>>>(inp, mds, (unsigned int*)d_out);
}